// round 3
// baseline (speedup 1.0000x reference)
#include <cuda_runtime.h>
#include <math.h>

#define NN 50000
#define EE 1600000
#define ET (EE + NN)
#define FIN 128
#define RD 16
#define HID 64
#define HEADS 4
#define D1 256
#define D2 64
#define NEG 0.2f
#define LN_EPS 1e-5f
#define IMIN (-2147483647 - 1)

// ---------------- scratch (__device__ globals; no allocations) ----------------
__device__ float g_xn[(size_t)NN * FIN];      // normalized node features
__device__ float g_xw1[(size_t)NN * D1];      // 51.2 MB
__device__ float g_out1[(size_t)NN * D1];     // 51.2 MB
__device__ float g_as1[NN * HEADS];
__device__ float g_ad1[NN * HEADS];
__device__ int   g_m1[NN * HEADS];
__device__ float g_den1[NN * HEADS];
__device__ float g_ex1[(size_t)ET * HEADS];   // 26.4 MB
__device__ float g_xw2[(size_t)NN * D2];
__device__ float g_out2[(size_t)NN * D2];
__device__ float g_as2[NN];
__device__ float g_ad2[NN];
__device__ int   g_m2[NN];
__device__ float g_den2[NN];
__device__ float g_ex2[ET];
__device__ float g_rc[D1];
__device__ int   g_smax;
__device__ float g_ssum;
__device__ float g_expw[NN];
__device__ int   g_src[ET];
__device__ int   g_dst[ET];
__device__ int   g_is64;

// ---------------- helpers ----------------
__device__ __forceinline__ int encf(float f) {
    int i = __float_as_int(f);
    return (i >= 0) ? i : (i ^ 0x7fffffff);
}
__device__ __forceinline__ float decf(int i) {
    return __int_as_float((i >= 0) ? i : (i ^ 0x7fffffff));
}
__device__ __forceinline__ float lrelu(float x) { return x > 0.f ? x : NEG * x; }
__device__ __forceinline__ float eluf(float x)  { return x > 0.f ? x : expm1f(x); }

__device__ __forceinline__ void red_add_v4(float* p, float4 v) {
    asm volatile("red.global.add.v4.f32 [%0], {%1,%2,%3,%4};"
                 :: "l"(p), "f"(v.x), "f"(v.y), "f"(v.z), "f"(v.w) : "memory");
}

// ---------------- edge dtype detect + convert ----------------
__global__ void detect_kernel(const void* ei) {
    if (threadIdx.x == 0 && blockIdx.x == 0) {
        const long long* p = (const long long*)ei;
        int is64 = 1;
        for (int i = 0; i < 64; i++) {
            long long v = p[i];
            if (v < 0 || v >= 2147483648LL) { is64 = 0; break; }
        }
        g_is64 = is64;
    }
}

__global__ void convert_kernel(const void* ei) {
    int e = blockIdx.x * blockDim.x + threadIdx.x;
    if (e >= ET) return;
    if (e < EE) {
        if (g_is64) {
            const long long* p = (const long long*)ei;
            g_src[e] = (int)p[e];
            g_dst[e] = (int)p[(size_t)EE + e];
        } else {
            const int* p = (const int*)ei;
            g_src[e] = p[e];
            g_dst[e] = p[EE + e];
        }
    } else {
        g_src[e] = g_dst[e] = e - EE;
    }
}

// ---------------- init ----------------
__global__ void init_kernel() {
    int i = blockIdx.x * blockDim.x + threadIdx.x;
    int stride = gridDim.x * blockDim.x;
    for (int t = i; t < NN * D1; t += stride) g_out1[t] = 0.f;
    for (int t = i; t < NN * D2; t += stride) g_out2[t] = 0.f;
    for (int t = i; t < NN * HEADS; t += stride) { g_den1[t] = 0.f; g_m1[t] = IMIN; }
    for (int t = i; t < NN; t += stride) { g_den2[t] = 0.f; g_m2[t] = IMIN; }
    if (i == 0) { g_smax = IMIN; g_ssum = 0.f; }
}

// ---------------- node LayerNorm: g_xn = LN(x)*gamma+beta ----------------
__global__ void ln_kernel(const float* __restrict__ X, const float* __restrict__ gamma,
                          const float* __restrict__ beta) {
    int n = blockIdx.x * (blockDim.x >> 5) + (threadIdx.x >> 5);
    if (n >= NN) return;
    int lane = threadIdx.x & 31;
    float4 v = ((const float4*)(X + (size_t)n * FIN))[lane];
    float s = v.x + v.y + v.z + v.w;
#pragma unroll
    for (int off = 16; off >= 1; off >>= 1) s += __shfl_xor_sync(0xffffffffu, s, off);
    float mu = s * (1.0f / FIN);
    float q = (v.x - mu) * (v.x - mu) + (v.y - mu) * (v.y - mu) +
              (v.z - mu) * (v.z - mu) + (v.w - mu) * (v.w - mu);
#pragma unroll
    for (int off = 16; off >= 1; off >>= 1) q += __shfl_xor_sync(0xffffffffu, q, off);
    float rstd = rsqrtf(q * (1.0f / FIN) + LN_EPS);
    float4 g = ((const float4*)gamma)[lane];
    float4 b = ((const float4*)beta)[lane];
    float4 o;
    o.x = (v.x - mu) * rstd * g.x + b.x;
    o.y = (v.y - mu) * rstd * g.y + b.y;
    o.z = (v.z - mu) * rstd * g.z + b.z;
    o.w = (v.w - mu) * rstd * g.w + b.w;
    ((float4*)(g_xn + (size_t)n * FIN))[lane] = o;
}

// ---------------- regime LN + rank-1 contribution ----------------
__global__ void prep_kernel(const float* __restrict__ reg, const float* __restrict__ rg,
                            const float* __restrict__ rb, const float* __restrict__ W1) {
    __shared__ float rn[RD];
    __shared__ float s_mu, s_rstd;
    int tid = threadIdx.x;
    if (tid == 0) {
        float s = 0.f;
        for (int k = 0; k < RD; k++) s += reg[k];
        float mu = s / RD;
        float q = 0.f;
        for (int k = 0; k < RD; k++) { float d = reg[k] - mu; q += d * d; }
        s_mu = mu; s_rstd = rsqrtf(q / RD + LN_EPS);
    }
    __syncthreads();
    if (tid < RD) rn[tid] = (reg[tid] - s_mu) * s_rstd * rg[tid] + rb[tid];
    __syncthreads();
    float acc = 0.f;
    for (int k = 0; k < RD; k++) acc += rn[k] * W1[(size_t)(FIN + k) * D1 + tid];
    g_rc[tid] = acc;
}

// ---------------- GEMM1: xw1 = g_xn @ W1[:128] + rc ----------------
// 256 threads, BM=64, BN=64, BK=64, K=128 in 2 chunks. Static smem.
__global__ void gemm1_kernel(const float* __restrict__ W1) {
    __shared__ float As[64][68];
    __shared__ float Bs[64][64];
    int row0 = blockIdx.y * 64;
    int col0 = blockIdx.x * 64;
    int tid = threadIdx.x;
    int ty4 = (tid >> 4) * 4, tx4 = (tid & 15) * 4;
    float acc[4][4] = {};
    for (int kc = 0; kc < 2; kc++) {
#pragma unroll
        for (int it = 0; it < 4; it++) {
            int flat = it * 1024 + tid * 4;
            int r = flat >> 6, c = flat & 63;
            float4 v = make_float4(0.f, 0.f, 0.f, 0.f);
            if (row0 + r < NN)
                v = *(const float4*)(g_xn + (size_t)(row0 + r) * FIN + kc * 64 + c);
            *(float4*)&As[r][c] = v;
            *(float4*)&Bs[r][c] = *(const float4*)(W1 + (size_t)(kc * 64 + r) * D1 + col0 + c);
        }
        __syncthreads();
#pragma unroll 4
        for (int k = 0; k < 64; k++) {
            float a[4];
#pragma unroll
            for (int i = 0; i < 4; i++) a[i] = As[ty4 + i][k];
            float4 b = *(const float4*)&Bs[k][tx4];
#pragma unroll
            for (int i = 0; i < 4; i++) {
                acc[i][0] += a[i] * b.x; acc[i][1] += a[i] * b.y;
                acc[i][2] += a[i] * b.z; acc[i][3] += a[i] * b.w;
            }
        }
        __syncthreads();
    }
    float4 rc = *(const float4*)&g_rc[col0 + tx4];
#pragma unroll
    for (int i = 0; i < 4; i++) {
        int r = row0 + ty4 + i;
        if (r < NN) {
            float4 o = make_float4(acc[i][0] + rc.x, acc[i][1] + rc.y,
                                   acc[i][2] + rc.z, acc[i][3] + rc.w);
            *(float4*)&g_xw1[(size_t)r * D1 + col0 + tx4] = o;
        }
    }
}

// ---------------- alpha1: per-node attention dots (4 heads) ----------------
__global__ void alpha1_kernel(const float* __restrict__ a_src, const float* __restrict__ a_dst) {
    int n = blockIdx.x * (blockDim.x >> 5) + (threadIdx.x >> 5);
    if (n >= NN) return;
    int lane = threadIdx.x & 31;
    const float4* xr = (const float4*)&g_xw1[(size_t)n * D1];
    float4 x0 = xr[lane], x1 = xr[lane + 32];
    float4 s0 = ((const float4*)a_src)[lane], s1 = ((const float4*)a_src)[lane + 32];
    float4 d0 = ((const float4*)a_dst)[lane], d1 = ((const float4*)a_dst)[lane + 32];
    float ss0 = x0.x * s0.x + x0.y * s0.y + x0.z * s0.z + x0.w * s0.w;
    float ss1 = x1.x * s1.x + x1.y * s1.y + x1.z * s1.z + x1.w * s1.w;
    float dd0 = x0.x * d0.x + x0.y * d0.y + x0.z * d0.z + x0.w * d0.w;
    float dd1 = x1.x * d1.x + x1.y * d1.y + x1.z * d1.z + x1.w * d1.w;
#pragma unroll
    for (int off = 8; off >= 1; off >>= 1) {
        ss0 += __shfl_xor_sync(0xffffffffu, ss0, off);
        ss1 += __shfl_xor_sync(0xffffffffu, ss1, off);
        dd0 += __shfl_xor_sync(0xffffffffu, dd0, off);
        dd1 += __shfl_xor_sync(0xffffffffu, dd1, off);
    }
    if ((lane & 15) == 0) {
        int g = lane >> 4;  // 0 or 1
        g_as1[n * 4 + g] = ss0;     g_as1[n * 4 + 2 + g] = ss1;
        g_ad1[n * 4 + g] = dd0;     g_ad1[n * 4 + 2 + g] = dd1;
    }
}

// ---------------- layer-1 edge passes ----------------
__global__ void edgeA1() {
    int e = blockIdx.x * blockDim.x + threadIdx.x;
    if (e >= ET) return;
    int s = g_src[e], d = g_dst[e];
    float4 as = *(const float4*)&g_as1[s * 4];
    float4 ad = *(const float4*)&g_ad1[d * 4];
    atomicMax(&g_m1[d * 4 + 0], encf(lrelu(as.x + ad.x)));
    atomicMax(&g_m1[d * 4 + 1], encf(lrelu(as.y + ad.y)));
    atomicMax(&g_m1[d * 4 + 2], encf(lrelu(as.z + ad.z)));
    atomicMax(&g_m1[d * 4 + 3], encf(lrelu(as.w + ad.w)));
}

__global__ void edgeB1() {
    int e = blockIdx.x * blockDim.x + threadIdx.x;
    if (e >= ET) return;
    int s = g_src[e], d = g_dst[e];
    float4 as = *(const float4*)&g_as1[s * 4];
    float4 ad = *(const float4*)&g_ad1[d * 4];
    int4 mm = *(const int4*)&g_m1[d * 4];
    float x0 = expf(lrelu(as.x + ad.x) - decf(mm.x));
    float x1 = expf(lrelu(as.y + ad.y) - decf(mm.y));
    float x2 = expf(lrelu(as.z + ad.z) - decf(mm.z));
    float x3 = expf(lrelu(as.w + ad.w) - decf(mm.w));
    *(float4*)&g_ex1[(size_t)e * 4] = make_float4(x0, x1, x2, x3);
    red_add_v4(&g_den1[d * 4], make_float4(x0, x1, x2, x3));
}

// warp per edge: 256 cols
__global__ void edgeC1() {
    int e = blockIdx.x * (blockDim.x >> 5) + (threadIdx.x >> 5);
    if (e >= ET) return;
    int lane = threadIdx.x & 31;
    int s = g_src[e], d = g_dst[e];
    float4 ex = *(const float4*)&g_ex1[(size_t)e * 4];
    float4 dn = *(const float4*)&g_den1[d * 4];
    float w0a = ex.x / dn.x, w1a = ex.y / dn.y, w2a = ex.z / dn.z, w3a = ex.w / dn.w;
    const float4* xs = (const float4*)&g_xw1[(size_t)s * D1];
    float* od = &g_out1[(size_t)d * D1];
    int h0 = lane >> 4;          // 0,1
    float wlo = (h0 == 0) ? w0a : w1a;
    float whi = (h0 == 0) ? w2a : w3a;
    float4 v0 = xs[lane];
    float4 v1 = xs[lane + 32];
    v0.x *= wlo; v0.y *= wlo; v0.z *= wlo; v0.w *= wlo;
    v1.x *= whi; v1.y *= whi; v1.z *= whi; v1.w *= whi;
    red_add_v4(od + 4 * lane, v0);
    red_add_v4(od + 128 + 4 * lane, v1);
}

// ---------------- GEMM2: xw2 = elu(out1 + b1) @ W2 ----------------
// BM=64, BN=64, K=256 in 4 chunks of 64.
__global__ void gemm2_kernel(const float* __restrict__ W2, const float* __restrict__ b1) {
    __shared__ float As[64][68];
    __shared__ float Bs[64][64];
    int row0 = blockIdx.x * 64;
    int tid = threadIdx.x;
    int ty4 = (tid >> 4) * 4, tx4 = (tid & 15) * 4;
    float acc[4][4] = {};
    for (int kc = 0; kc < 4; kc++) {
#pragma unroll
        for (int it = 0; it < 4; it++) {
            int flat = it * 1024 + tid * 4;
            int r = flat >> 6, c = flat & 63;
            int gc = kc * 64 + c;
            float4 v = make_float4(0.f, 0.f, 0.f, 0.f);
            if (row0 + r < NN) {
                v = *(const float4*)&g_out1[(size_t)(row0 + r) * D1 + gc];
                float4 bb = *(const float4*)&b1[gc];
                v.x = eluf(v.x + bb.x); v.y = eluf(v.y + bb.y);
                v.z = eluf(v.z + bb.z); v.w = eluf(v.w + bb.w);
            }
            *(float4*)&As[r][c] = v;
            *(float4*)&Bs[r][c] = *(const float4*)(W2 + (size_t)(kc * 64 + r) * D2 + c);
        }
        __syncthreads();
#pragma unroll 4
        for (int k = 0; k < 64; k++) {
            float a[4];
#pragma unroll
            for (int i = 0; i < 4; i++) a[i] = As[ty4 + i][k];
            float4 b = *(const float4*)&Bs[k][tx4];
#pragma unroll
            for (int i = 0; i < 4; i++) {
                acc[i][0] += a[i] * b.x; acc[i][1] += a[i] * b.y;
                acc[i][2] += a[i] * b.z; acc[i][3] += a[i] * b.w;
            }
        }
        __syncthreads();
    }
#pragma unroll
    for (int i = 0; i < 4; i++) {
        int r = row0 + ty4 + i;
        if (r < NN) {
            float4 o = make_float4(acc[i][0], acc[i][1], acc[i][2], acc[i][3]);
            *(float4*)&g_xw2[(size_t)r * D2 + tx4] = o;
        }
    }
}

// ---------------- alpha2 ----------------
__global__ void alpha2_kernel(const float* __restrict__ a_src, const float* __restrict__ a_dst) {
    int n = blockIdx.x * (blockDim.x >> 5) + (threadIdx.x >> 5);
    if (n >= NN) return;
    int lane = threadIdx.x & 31;
    float2 x = ((const float2*)&g_xw2[(size_t)n * D2])[lane];
    float2 s = ((const float2*)a_src)[lane];
    float2 d = ((const float2*)a_dst)[lane];
    float ss = x.x * s.x + x.y * s.y;
    float dd = x.x * d.x + x.y * d.y;
#pragma unroll
    for (int off = 16; off >= 1; off >>= 1) {
        ss += __shfl_xor_sync(0xffffffffu, ss, off);
        dd += __shfl_xor_sync(0xffffffffu, dd, off);
    }
    if (lane == 0) { g_as2[n] = ss; g_ad2[n] = dd; }
}

// ---------------- layer-2 edge passes ----------------
__global__ void edgeA2() {
    int e = blockIdx.x * blockDim.x + threadIdx.x;
    if (e >= ET) return;
    int s = g_src[e], d = g_dst[e];
    float ev = lrelu(g_as2[s] + g_ad2[d]);
    atomicMax(&g_m2[d], encf(ev));
}

__global__ void edgeB2() {
    int e = blockIdx.x * blockDim.x + threadIdx.x;
    if (e >= ET) return;
    int s = g_src[e], d = g_dst[e];
    float ev = lrelu(g_as2[s] + g_ad2[d]);
    float x = expf(ev - decf(g_m2[d]));
    g_ex2[e] = x;
    atomicAdd(&g_den2[d], x);
}

// 16 lanes per edge: 64 cols
__global__ void edgeC2() {
    int e = blockIdx.x * (blockDim.x >> 4) + (threadIdx.x >> 4);
    if (e >= ET) return;
    int l = threadIdx.x & 15;
    int s = g_src[e], d = g_dst[e];
    float w = g_ex2[e] / g_den2[d];
    float4 v = ((const float4*)&g_xw2[(size_t)s * D2])[l];
    v.x *= w; v.y *= w; v.z *= w; v.w *= w;
    red_add_v4(&g_out2[(size_t)d * D2 + 4 * l], v);
}

// ---------------- logits + global softmax ----------------
__global__ void logits_kernel(const float* __restrict__ b2, const float* __restrict__ Wout,
                              const float* __restrict__ bout, float* __restrict__ out) {
    int n = blockIdx.x * (blockDim.x >> 5) + (threadIdx.x >> 5);
    if (n >= NN) return;
    int lane = threadIdx.x & 31;
    float2 v = ((const float2*)&g_out2[(size_t)n * D2])[lane];
    float2 bb = ((const float2*)b2)[lane];
    float2 w = ((const float2*)Wout)[lane];
    float p = eluf(v.x + bb.x) * w.x + eluf(v.y + bb.y) * w.y;
#pragma unroll
    for (int off = 16; off >= 1; off >>= 1)
        p += __shfl_xor_sync(0xffffffffu, p, off);
    if (lane == 0) {
        float logit = p + bout[0];
        out[NN + n] = logit;
        atomicMax(&g_smax, encf(logit));
    }
}

__global__ void expw_kernel(const float* __restrict__ out) {
    int n = blockIdx.x * blockDim.x + threadIdx.x;
    if (n >= NN) return;
    float mx = decf(g_smax);
    float ex = expf(out[NN + n] - mx);
    g_expw[n] = ex;
    atomicAdd(&g_ssum, ex);
}

__global__ void weights_kernel(float* __restrict__ out) {
    int n = blockIdx.x * blockDim.x + threadIdx.x;
    if (n >= NN) return;
    out[n] = g_expw[n] / g_ssum;
}

// ---------------- launch ----------------
extern "C" void kernel_launch(void* const* d_in, const int* in_sizes, int n_in,
                              void* d_out, int out_size) {
    const float* x      = (const float*)d_in[0];
    const void*  ei     = (const void*)d_in[1];
    const float* reg    = (const float*)d_in[2];
    const float* ngamma = (const float*)d_in[3];
    const float* nbeta  = (const float*)d_in[4];
    const float* rgamma = (const float*)d_in[5];
    const float* rbeta  = (const float*)d_in[6];
    const float* W1     = (const float*)d_in[7];
    const float* a_s1   = (const float*)d_in[8];
    const float* a_d1   = (const float*)d_in[9];
    const float* b1     = (const float*)d_in[10];
    const float* W2     = (const float*)d_in[11];
    const float* a_s2   = (const float*)d_in[12];
    const float* a_d2   = (const float*)d_in[13];
    const float* b2     = (const float*)d_in[14];
    const float* Wout   = (const float*)d_in[15];
    const float* bout   = (const float*)d_in[16];
    float* out = (float*)d_out;

    detect_kernel<<<1, 32>>>(ei);
    convert_kernel<<<(ET + 255) / 256, 256>>>(ei);
    init_kernel<<<2048, 256>>>();
    ln_kernel<<<(NN + 7) / 8, 256>>>(x, ngamma, nbeta);
    prep_kernel<<<1, 256>>>(reg, rgamma, rbeta, W1);

    dim3 g1(4, (NN + 63) / 64);
    gemm1_kernel<<<g1, 256>>>(W1);

    alpha1_kernel<<<(NN + 7) / 8, 256>>>(a_s1, a_d1);

    int ebl = (ET + 255) / 256;
    edgeA1<<<ebl, 256>>>();
    edgeB1<<<ebl, 256>>>();
    edgeC1<<<(ET + 7) / 8, 256>>>();

    gemm2_kernel<<<(NN + 63) / 64, 256>>>(W2, b1);

    alpha2_kernel<<<(NN + 7) / 8, 256>>>(a_s2, a_d2);
    edgeA2<<<ebl, 256>>>();
    edgeB2<<<ebl, 256>>>();
    edgeC2<<<(ET + 15) / 16, 256>>>();

    logits_kernel<<<(NN + 7) / 8, 256>>>(b2, Wout, bout, out);
    expw_kernel<<<(NN + 255) / 256, 256>>>(out);
    weights_kernel<<<(NN + 255) / 256, 256>>>(out);
}

// round 4
// speedup vs baseline: 1.7703x; 1.7703x over previous
#include <cuda_runtime.h>
#include <math.h>

#define NN 50000
#define EE 1600000
#define ET (EE + NN)
#define FIN 128
#define RD 16
#define HID 64
#define HEADS 4
#define D1 256
#define D2 64
#define NEG 0.2f
#define LN_EPS 1e-5f
#define IMIN (-2147483647 - 1)
#define NEGINF (-3.402823466e38f)

// ---------------- scratch (__device__ globals; no allocations) ----------------
__device__ float g_xn[(size_t)NN * FIN];
__device__ float g_xw1[(size_t)NN * D1];      // 51.2 MB
__device__ float g_h1[(size_t)NN * D1];       // elu(agg1 + b1)
__device__ float g_as1[NN * HEADS];
__device__ float g_ad1[NN * HEADS];
__device__ float g_xw2[(size_t)NN * D2];
__device__ float g_as2[NN];
__device__ float g_ad2[NN];
__device__ float g_rc[D1];
__device__ int   g_smax;
__device__ float g_ssum;
__device__ float g_expw[NN];
__device__ int   g_src[ET];
__device__ int   g_dst[ET];
__device__ int   g_deg[NN];
__device__ int   g_rowstart[NN + 1];
__device__ int   g_cursor[NN];
__device__ int   g_csrsrc[ET];
__device__ int   g_is64;

// ---------------- helpers ----------------
__device__ __forceinline__ int encf(float f) {
    int i = __float_as_int(f);
    return (i >= 0) ? i : (i ^ 0x7fffffff);
}
__device__ __forceinline__ float decf(int i) {
    return __int_as_float((i >= 0) ? i : (i ^ 0x7fffffff));
}
__device__ __forceinline__ float lrelu(float x) { return x > 0.f ? x : NEG * x; }
__device__ __forceinline__ float eluf(float x)  { return x > 0.f ? x : expm1f(x); }

// ---------------- edge dtype detect ----------------
__global__ void detect_kernel(const void* ei) {
    if (threadIdx.x == 0 && blockIdx.x == 0) {
        const long long* p = (const long long*)ei;
        int is64 = 1;
        for (int i = 0; i < 64; i++) {
            long long v = p[i];
            if (v < 0 || v >= 2147483648LL) { is64 = 0; break; }
        }
        g_is64 = is64;
    }
}

// ---------------- init (small buffers only) ----------------
__global__ void init_kernel() {
    int i = blockIdx.x * blockDim.x + threadIdx.x;
    int stride = gridDim.x * blockDim.x;
    for (int t = i; t < NN; t += stride) { g_deg[t] = 0; g_cursor[t] = 0; }
    if (i == 0) { g_smax = IMIN; g_ssum = 0.f; }
}

// ---------------- convert edges + degree histogram ----------------
__global__ void convert_kernel(const void* ei) {
    int e = blockIdx.x * blockDim.x + threadIdx.x;
    if (e >= ET) return;
    int s, d;
    if (e < EE) {
        if (g_is64) {
            const long long* p = (const long long*)ei;
            s = (int)p[e];
            d = (int)p[(size_t)EE + e];
        } else {
            const int* p = (const int*)ei;
            s = p[e];
            d = p[EE + e];
        }
    } else {
        s = d = e - EE;
    }
    g_src[e] = s;
    g_dst[e] = d;
    atomicAdd(&g_deg[d], 1);
}

// ---------------- exclusive scan of degrees (single block) ----------------
__global__ void scan_kernel() {
    __shared__ int part[1024];
    int t = threadIdx.x;
    const int C = (NN + 1023) / 1024;  // 49
    int base = t * C;
    int sum = 0;
    for (int j = 0; j < C; j++) {
        int idx = base + j;
        if (idx < NN) sum += g_deg[idx];
    }
    part[t] = sum;
    __syncthreads();
    for (int off = 1; off < 1024; off <<= 1) {
        int v = (t >= off) ? part[t - off] : 0;
        __syncthreads();
        part[t] += v;
        __syncthreads();
    }
    int run = part[t] - sum;  // exclusive offset
    for (int j = 0; j < C; j++) {
        int idx = base + j;
        if (idx < NN) { g_rowstart[idx] = run; run += g_deg[idx]; }
    }
    if (t == 1023) g_rowstart[NN] = ET;
}

// ---------------- scatter: CSR src list grouped by dst ----------------
__global__ void scatter_kernel() {
    int e = blockIdx.x * blockDim.x + threadIdx.x;
    if (e >= ET) return;
    int d = g_dst[e];
    int pos = atomicAdd(&g_cursor[d], 1);
    g_csrsrc[g_rowstart[d] + pos] = g_src[e];
}

// ---------------- node LayerNorm ----------------
__global__ void ln_kernel(const float* __restrict__ X, const float* __restrict__ gamma,
                          const float* __restrict__ beta) {
    int n = blockIdx.x * (blockDim.x >> 5) + (threadIdx.x >> 5);
    if (n >= NN) return;
    int lane = threadIdx.x & 31;
    float4 v = ((const float4*)(X + (size_t)n * FIN))[lane];
    float s = v.x + v.y + v.z + v.w;
#pragma unroll
    for (int off = 16; off >= 1; off >>= 1) s += __shfl_xor_sync(0xffffffffu, s, off);
    float mu = s * (1.0f / FIN);
    float q = (v.x - mu) * (v.x - mu) + (v.y - mu) * (v.y - mu) +
              (v.z - mu) * (v.z - mu) + (v.w - mu) * (v.w - mu);
#pragma unroll
    for (int off = 16; off >= 1; off >>= 1) q += __shfl_xor_sync(0xffffffffu, q, off);
    float rstd = rsqrtf(q * (1.0f / FIN) + LN_EPS);
    float4 g = ((const float4*)gamma)[lane];
    float4 b = ((const float4*)beta)[lane];
    float4 o;
    o.x = (v.x - mu) * rstd * g.x + b.x;
    o.y = (v.y - mu) * rstd * g.y + b.y;
    o.z = (v.z - mu) * rstd * g.z + b.z;
    o.w = (v.w - mu) * rstd * g.w + b.w;
    ((float4*)(g_xn + (size_t)n * FIN))[lane] = o;
}

// ---------------- regime LN + rank-1 contribution ----------------
__global__ void prep_kernel(const float* __restrict__ reg, const float* __restrict__ rg,
                            const float* __restrict__ rb, const float* __restrict__ W1) {
    __shared__ float rn[RD];
    __shared__ float s_mu, s_rstd;
    int tid = threadIdx.x;
    if (tid == 0) {
        float s = 0.f;
        for (int k = 0; k < RD; k++) s += reg[k];
        float mu = s / RD;
        float q = 0.f;
        for (int k = 0; k < RD; k++) { float d = reg[k] - mu; q += d * d; }
        s_mu = mu; s_rstd = rsqrtf(q / RD + LN_EPS);
    }
    __syncthreads();
    if (tid < RD) rn[tid] = (reg[tid] - s_mu) * s_rstd * rg[tid] + rb[tid];
    __syncthreads();
    float acc = 0.f;
    for (int k = 0; k < RD; k++) acc += rn[k] * W1[(size_t)(FIN + k) * D1 + tid];
    g_rc[tid] = acc;
}

// ---------------- GEMM1: xw1 = g_xn @ W1[:128] + rc ----------------
__global__ void gemm1_kernel(const float* __restrict__ W1) {
    __shared__ float As[64][68];
    __shared__ float Bs[64][64];
    int row0 = blockIdx.y * 64;
    int col0 = blockIdx.x * 64;
    int tid = threadIdx.x;
    int ty4 = (tid >> 4) * 4, tx4 = (tid & 15) * 4;
    float acc[4][4] = {};
    for (int kc = 0; kc < 2; kc++) {
#pragma unroll
        for (int it = 0; it < 4; it++) {
            int flat = it * 1024 + tid * 4;
            int r = flat >> 6, c = flat & 63;
            float4 v = make_float4(0.f, 0.f, 0.f, 0.f);
            if (row0 + r < NN)
                v = *(const float4*)(g_xn + (size_t)(row0 + r) * FIN + kc * 64 + c);
            *(float4*)&As[r][c] = v;
            *(float4*)&Bs[r][c] = *(const float4*)(W1 + (size_t)(kc * 64 + r) * D1 + col0 + c);
        }
        __syncthreads();
#pragma unroll 4
        for (int k = 0; k < 64; k++) {
            float a[4];
#pragma unroll
            for (int i = 0; i < 4; i++) a[i] = As[ty4 + i][k];
            float4 b = *(const float4*)&Bs[k][tx4];
#pragma unroll
            for (int i = 0; i < 4; i++) {
                acc[i][0] += a[i] * b.x; acc[i][1] += a[i] * b.y;
                acc[i][2] += a[i] * b.z; acc[i][3] += a[i] * b.w;
            }
        }
        __syncthreads();
    }
    float4 rc = *(const float4*)&g_rc[col0 + tx4];
#pragma unroll
    for (int i = 0; i < 4; i++) {
        int r = row0 + ty4 + i;
        if (r < NN) {
            float4 o = make_float4(acc[i][0] + rc.x, acc[i][1] + rc.y,
                                   acc[i][2] + rc.z, acc[i][3] + rc.w);
            *(float4*)&g_xw1[(size_t)r * D1 + col0 + tx4] = o;
        }
    }
}

// ---------------- alpha1: per-node attention dots (4 heads) ----------------
__global__ void alpha1_kernel(const float* __restrict__ a_src, const float* __restrict__ a_dst) {
    int n = blockIdx.x * (blockDim.x >> 5) + (threadIdx.x >> 5);
    if (n >= NN) return;
    int lane = threadIdx.x & 31;
    const float4* xr = (const float4*)&g_xw1[(size_t)n * D1];
    float4 x0 = xr[lane], x1 = xr[lane + 32];
    float4 s0 = ((const float4*)a_src)[lane], s1 = ((const float4*)a_src)[lane + 32];
    float4 d0 = ((const float4*)a_dst)[lane], d1 = ((const float4*)a_dst)[lane + 32];
    float ss0 = x0.x * s0.x + x0.y * s0.y + x0.z * s0.z + x0.w * s0.w;
    float ss1 = x1.x * s1.x + x1.y * s1.y + x1.z * s1.z + x1.w * s1.w;
    float dd0 = x0.x * d0.x + x0.y * d0.y + x0.z * d0.z + x0.w * d0.w;
    float dd1 = x1.x * d1.x + x1.y * d1.y + x1.z * d1.z + x1.w * d1.w;
#pragma unroll
    for (int off = 8; off >= 1; off >>= 1) {
        ss0 += __shfl_xor_sync(0xffffffffu, ss0, off);
        ss1 += __shfl_xor_sync(0xffffffffu, ss1, off);
        dd0 += __shfl_xor_sync(0xffffffffu, dd0, off);
        dd1 += __shfl_xor_sync(0xffffffffu, dd1, off);
    }
    if ((lane & 15) == 0) {
        int g = lane >> 4;
        g_as1[n * 4 + g] = ss0;     g_as1[n * 4 + 2 + g] = ss1;
        g_ad1[n * 4 + g] = dd0;     g_ad1[n * 4 + 2 + g] = dd1;
    }
}

// ---------------- fused layer-1 aggregation: warp per dst node ----------------
// segment softmax (max, exp-sum) + weighted gather of xw1[src], write h1 = elu(agg + b1)
__global__ void agg1_kernel(const float* __restrict__ b1) {
    __shared__ float4 s_ex[8][32];
    __shared__ int    s_src[8][32];
    int warp = threadIdx.x >> 5;
    int lane = threadIdx.x & 31;
    int n = blockIdx.x * 8 + warp;
    if (n >= NN) return;
    int beg = g_rowstart[n], end = g_rowstart[n + 1];
    float4 ad = *(const float4*)&g_ad1[n * 4];

    // pass 1: per-head segment max
    float4 mx = make_float4(NEGINF, NEGINF, NEGINF, NEGINF);
    for (int i = beg + lane; i < end; i += 32) {
        int s = g_csrsrc[i];
        float4 as = *(const float4*)&g_as1[s * 4];
        mx.x = fmaxf(mx.x, lrelu(as.x + ad.x));
        mx.y = fmaxf(mx.y, lrelu(as.y + ad.y));
        mx.z = fmaxf(mx.z, lrelu(as.z + ad.z));
        mx.w = fmaxf(mx.w, lrelu(as.w + ad.w));
    }
#pragma unroll
    for (int off = 16; off >= 1; off >>= 1) {
        mx.x = fmaxf(mx.x, __shfl_xor_sync(0xffffffffu, mx.x, off));
        mx.y = fmaxf(mx.y, __shfl_xor_sync(0xffffffffu, mx.y, off));
        mx.z = fmaxf(mx.z, __shfl_xor_sync(0xffffffffu, mx.z, off));
        mx.w = fmaxf(mx.w, __shfl_xor_sync(0xffffffffu, mx.w, off));
    }

    // pass 2: exp weights + weighted feature accumulation
    float4 den = make_float4(0.f, 0.f, 0.f, 0.f);
    float4 accLo = make_float4(0.f, 0.f, 0.f, 0.f);
    float4 accHi = make_float4(0.f, 0.f, 0.f, 0.f);
    for (int chunk = beg; chunk < end; chunk += 32) {
        int m = min(32, end - chunk);
        if (lane < m) {
            int s = g_csrsrc[chunk + lane];
            float4 as = *(const float4*)&g_as1[s * 4];
            float4 ex;
            ex.x = expf(lrelu(as.x + ad.x) - mx.x);
            ex.y = expf(lrelu(as.y + ad.y) - mx.y);
            ex.z = expf(lrelu(as.z + ad.z) - mx.z);
            ex.w = expf(lrelu(as.w + ad.w) - mx.w);
            den.x += ex.x; den.y += ex.y; den.z += ex.z; den.w += ex.w;
            s_ex[warp][lane] = ex;
            s_src[warp][lane] = s;
        }
        __syncwarp();
        for (int j = 0; j < m; j++) {
            int s = s_src[warp][j];
            float4 ex = s_ex[warp][j];
            float wlo = (lane < 16) ? ex.x : ex.y;
            float whi = (lane < 16) ? ex.z : ex.w;
            const float4* xs = (const float4*)&g_xw1[(size_t)s * D1];
            float4 v0 = xs[lane];
            float4 v1 = xs[lane + 32];
            accLo.x += wlo * v0.x; accLo.y += wlo * v0.y;
            accLo.z += wlo * v0.z; accLo.w += wlo * v0.w;
            accHi.x += whi * v1.x; accHi.y += whi * v1.y;
            accHi.z += whi * v1.z; accHi.w += whi * v1.w;
        }
        __syncwarp();
    }
    // reduce denominators
#pragma unroll
    for (int off = 16; off >= 1; off >>= 1) {
        den.x += __shfl_xor_sync(0xffffffffu, den.x, off);
        den.y += __shfl_xor_sync(0xffffffffu, den.y, off);
        den.z += __shfl_xor_sync(0xffffffffu, den.z, off);
        den.w += __shfl_xor_sync(0xffffffffu, den.w, off);
    }
    float rlo = 1.0f / ((lane < 16) ? den.x : den.y);
    float rhi = 1.0f / ((lane < 16) ? den.z : den.w);
    float4 blo = ((const float4*)b1)[lane];
    float4 bhi = ((const float4*)b1)[lane + 32];
    float4 o0, o1;
    o0.x = eluf(accLo.x * rlo + blo.x); o0.y = eluf(accLo.y * rlo + blo.y);
    o0.z = eluf(accLo.z * rlo + blo.z); o0.w = eluf(accLo.w * rlo + blo.w);
    o1.x = eluf(accHi.x * rhi + bhi.x); o1.y = eluf(accHi.y * rhi + bhi.y);
    o1.z = eluf(accHi.z * rhi + bhi.z); o1.w = eluf(accHi.w * rhi + bhi.w);
    float4* od = (float4*)&g_h1[(size_t)n * D1];
    od[lane] = o0;
    od[lane + 32] = o1;
}

// ---------------- GEMM2: xw2 = g_h1 @ W2 ----------------
__global__ void gemm2_kernel(const float* __restrict__ W2) {
    __shared__ float As[64][68];
    __shared__ float Bs[64][64];
    int row0 = blockIdx.x * 64;
    int tid = threadIdx.x;
    int ty4 = (tid >> 4) * 4, tx4 = (tid & 15) * 4;
    float acc[4][4] = {};
    for (int kc = 0; kc < 4; kc++) {
#pragma unroll
        for (int it = 0; it < 4; it++) {
            int flat = it * 1024 + tid * 4;
            int r = flat >> 6, c = flat & 63;
            float4 v = make_float4(0.f, 0.f, 0.f, 0.f);
            if (row0 + r < NN)
                v = *(const float4*)&g_h1[(size_t)(row0 + r) * D1 + kc * 64 + c];
            *(float4*)&As[r][c] = v;
            *(float4*)&Bs[r][c] = *(const float4*)(W2 + (size_t)(kc * 64 + r) * D2 + c);
        }
        __syncthreads();
#pragma unroll 4
        for (int k = 0; k < 64; k++) {
            float a[4];
#pragma unroll
            for (int i = 0; i < 4; i++) a[i] = As[ty4 + i][k];
            float4 b = *(const float4*)&Bs[k][tx4];
#pragma unroll
            for (int i = 0; i < 4; i++) {
                acc[i][0] += a[i] * b.x; acc[i][1] += a[i] * b.y;
                acc[i][2] += a[i] * b.z; acc[i][3] += a[i] * b.w;
            }
        }
        __syncthreads();
    }
#pragma unroll
    for (int i = 0; i < 4; i++) {
        int r = row0 + ty4 + i;
        if (r < NN) {
            float4 o = make_float4(acc[i][0], acc[i][1], acc[i][2], acc[i][3]);
            *(float4*)&g_xw2[(size_t)r * D2 + tx4] = o;
        }
    }
}

// ---------------- alpha2 ----------------
__global__ void alpha2_kernel(const float* __restrict__ a_src, const float* __restrict__ a_dst) {
    int n = blockIdx.x * (blockDim.x >> 5) + (threadIdx.x >> 5);
    if (n >= NN) return;
    int lane = threadIdx.x & 31;
    float2 x = ((const float2*)&g_xw2[(size_t)n * D2])[lane];
    float2 s = ((const float2*)a_src)[lane];
    float2 d = ((const float2*)a_dst)[lane];
    float ss = x.x * s.x + x.y * s.y;
    float dd = x.x * d.x + x.y * d.y;
#pragma unroll
    for (int off = 16; off >= 1; off >>= 1) {
        ss += __shfl_xor_sync(0xffffffffu, ss, off);
        dd += __shfl_xor_sync(0xffffffffu, dd, off);
    }
    if (lane == 0) { g_as2[n] = ss; g_ad2[n] = dd; }
}

// ---------------- fused layer-2 aggregation + logits: warp per dst node ----------------
__global__ void agg2_kernel(const float* __restrict__ b2, const float* __restrict__ Wout,
                            const float* __restrict__ bout, float* __restrict__ out) {
    __shared__ float s_ex[8][32];
    __shared__ int   s_src[8][32];
    int warp = threadIdx.x >> 5;
    int lane = threadIdx.x & 31;
    int n = blockIdx.x * 8 + warp;
    if (n >= NN) return;
    int beg = g_rowstart[n], end = g_rowstart[n + 1];
    float ad = g_ad2[n];

    float mx = NEGINF;
    for (int i = beg + lane; i < end; i += 32) {
        int s = g_csrsrc[i];
        mx = fmaxf(mx, lrelu(g_as2[s] + ad));
    }
#pragma unroll
    for (int off = 16; off >= 1; off >>= 1)
        mx = fmaxf(mx, __shfl_xor_sync(0xffffffffu, mx, off));

    float den = 0.f;
    float2 acc = make_float2(0.f, 0.f);
    for (int chunk = beg; chunk < end; chunk += 32) {
        int m = min(32, end - chunk);
        if (lane < m) {
            int s = g_csrsrc[chunk + lane];
            float ex = expf(lrelu(g_as2[s] + ad) - mx);
            den += ex;
            s_ex[warp][lane] = ex;
            s_src[warp][lane] = s;
        }
        __syncwarp();
        for (int j = 0; j < m; j++) {
            int s = s_src[warp][j];
            float w = s_ex[warp][j];
            float2 v = ((const float2*)&g_xw2[(size_t)s * D2])[lane];
            acc.x += w * v.x;
            acc.y += w * v.y;
        }
        __syncwarp();
    }
#pragma unroll
    for (int off = 16; off >= 1; off >>= 1)
        den += __shfl_xor_sync(0xffffffffu, den, off);
    float r = 1.0f / den;
    float2 bb = ((const float2*)b2)[lane];
    float2 w = ((const float2*)Wout)[lane];
    float p = eluf(acc.x * r + bb.x) * w.x + eluf(acc.y * r + bb.y) * w.y;
#pragma unroll
    for (int off = 16; off >= 1; off >>= 1)
        p += __shfl_xor_sync(0xffffffffu, p, off);
    if (lane == 0) {
        float logit = p + bout[0];
        out[NN + n] = logit;
        atomicMax(&g_smax, encf(logit));
    }
}

// ---------------- global softmax epilogue ----------------
__global__ void expw_kernel(const float* __restrict__ out) {
    int n = blockIdx.x * blockDim.x + threadIdx.x;
    if (n >= NN) return;
    float mx = decf(g_smax);
    float ex = expf(out[NN + n] - mx);
    g_expw[n] = ex;
    atomicAdd(&g_ssum, ex);
}

__global__ void weights_kernel(float* __restrict__ out) {
    int n = blockIdx.x * blockDim.x + threadIdx.x;
    if (n >= NN) return;
    out[n] = g_expw[n] / g_ssum;
}

// ---------------- launch ----------------
extern "C" void kernel_launch(void* const* d_in, const int* in_sizes, int n_in,
                              void* d_out, int out_size) {
    const float* x      = (const float*)d_in[0];
    const void*  ei     = (const void*)d_in[1];
    const float* reg    = (const float*)d_in[2];
    const float* ngamma = (const float*)d_in[3];
    const float* nbeta  = (const float*)d_in[4];
    const float* rgamma = (const float*)d_in[5];
    const float* rbeta  = (const float*)d_in[6];
    const float* W1     = (const float*)d_in[7];
    const float* a_s1   = (const float*)d_in[8];
    const float* a_d1   = (const float*)d_in[9];
    const float* b1     = (const float*)d_in[10];
    const float* W2     = (const float*)d_in[11];
    const float* a_s2   = (const float*)d_in[12];
    const float* a_d2   = (const float*)d_in[13];
    const float* b2     = (const float*)d_in[14];
    const float* Wout   = (const float*)d_in[15];
    const float* bout   = (const float*)d_in[16];
    float* out = (float*)d_out;

    detect_kernel<<<1, 32>>>(ei);
    init_kernel<<<256, 256>>>();
    convert_kernel<<<(ET + 255) / 256, 256>>>(ei);
    scan_kernel<<<1, 1024>>>();
    scatter_kernel<<<(ET + 255) / 256, 256>>>();

    ln_kernel<<<(NN + 7) / 8, 256>>>(x, ngamma, nbeta);
    prep_kernel<<<1, 256>>>(reg, rgamma, rbeta, W1);

    dim3 g1(4, (NN + 63) / 64);
    gemm1_kernel<<<g1, 256>>>(W1);
    alpha1_kernel<<<(NN + 7) / 8, 256>>>(a_s1, a_d1);

    agg1_kernel<<<(NN + 7) / 8, 256>>>(b1);

    gemm2_kernel<<<(NN + 63) / 64, 256>>>(W2);
    alpha2_kernel<<<(NN + 7) / 8, 256>>>(a_s2, a_d2);

    agg2_kernel<<<(NN + 7) / 8, 256>>>(b2, Wout, bout, out);

    expw_kernel<<<(NN + 255) / 256, 256>>>(out);
    weights_kernel<<<(NN + 255) / 256, 256>>>(out);
}

// round 5
// speedup vs baseline: 1.9330x; 1.0919x over previous
#include <cuda_runtime.h>
#include <cuda_bf16.h>
#include <math.h>

#define NN 50000
#define EE 1600000
#define ET (EE + NN)
#define FIN 128
#define RD 16
#define HID 64
#define HEADS 4
#define D1 256
#define D2 64
#define NEG 0.2f
#define LN_EPS 1e-5f
#define IMIN (-2147483647 - 1)
#define NEGINF (-3.402823466e38f)
#define NBLK 196   // ceil(NN/256)

// ---------------- scratch ----------------
__device__ float g_xn[(size_t)NN * FIN];
__device__ float g_xw1[(size_t)NN * D1];
__device__ __nv_bfloat16 g_xw1b[(size_t)NN * D1];
__device__ float g_h1[(size_t)NN * D1];
__device__ float g_as1[NN * HEADS];
__device__ float g_ad1[NN * HEADS];
__device__ float g_xw2[(size_t)NN * D2];
__device__ __nv_bfloat16 g_xw2b[(size_t)NN * D2];
__device__ float g_as2[NN];
__device__ float g_ad2[NN];
__device__ float g_rc[D1];
__device__ int   g_smax;
__device__ float g_ssum;
__device__ float g_expw[NN];
__device__ int   g_src[ET];
__device__ int   g_dst[ET];
__device__ int   g_deg[NN];
__device__ int   g_rowstart[NN + 1];
__device__ int   g_cursor[NN];
__device__ int   g_csrsrc[ET];
__device__ int   g_bsum[256];
__device__ int   g_is64;

// ---------------- helpers ----------------
__device__ __forceinline__ int encf(float f) {
    int i = __float_as_int(f);
    return (i >= 0) ? i : (i ^ 0x7fffffff);
}
__device__ __forceinline__ float decf(int i) {
    return __int_as_float((i >= 0) ? i : (i ^ 0x7fffffff));
}
__device__ __forceinline__ float lrelu(float x) { return x > 0.f ? x : NEG * x; }
__device__ __forceinline__ float eluf(float x)  { return x > 0.f ? x : expm1f(x); }

// ---------------- edge dtype detect ----------------
__global__ void detect_kernel(const void* ei) {
    if (threadIdx.x == 0 && blockIdx.x == 0) {
        const long long* p = (const long long*)ei;
        int is64 = 1;
        for (int i = 0; i < 64; i++) {
            long long v = p[i];
            if (v < 0 || v >= 2147483648LL) { is64 = 0; break; }
        }
        g_is64 = is64;
    }
}

// ---------------- init ----------------
__global__ void init_kernel() {
    int i = blockIdx.x * blockDim.x + threadIdx.x;
    int stride = gridDim.x * blockDim.x;
    for (int t = i; t < NN; t += stride) { g_deg[t] = 0; g_cursor[t] = 0; }
    if (i == 0) { g_smax = IMIN; g_ssum = 0.f; }
}

// ---------------- convert edges + degree histogram ----------------
__global__ void convert_kernel(const void* ei) {
    int e = blockIdx.x * blockDim.x + threadIdx.x;
    if (e >= ET) return;
    int s, d;
    if (e < EE) {
        if (g_is64) {
            const long long* p = (const long long*)ei;
            s = (int)p[e];
            d = (int)p[(size_t)EE + e];
        } else {
            const int* p = (const int*)ei;
            s = p[e];
            d = p[EE + e];
        }
    } else {
        s = d = e - EE;
    }
    g_src[e] = s;
    g_dst[e] = d;
    atomicAdd(&g_deg[d], 1);
}

// ---------------- 3-phase coalesced exclusive scan ----------------
__global__ void scan1_kernel() {      // per-block sums
    __shared__ int sm[256];
    int t = threadIdx.x, b = blockIdx.x;
    int idx = b * 256 + t;
    int v = (idx < NN) ? g_deg[idx] : 0;
    sm[t] = v;
    __syncthreads();
    for (int off = 128; off >= 1; off >>= 1) {
        if (t < off) sm[t] += sm[t + off];
        __syncthreads();
    }
    if (t == 0) g_bsum[b] = sm[0];
}

__global__ void scan2_kernel() {      // exclusive scan of 196 block sums
    __shared__ int sm[256];
    int t = threadIdx.x;
    int v = (t < NBLK) ? g_bsum[t] : 0;
    sm[t] = v;
    __syncthreads();
    for (int off = 1; off < 256; off <<= 1) {
        int u = (t >= off) ? sm[t - off] : 0;
        __syncthreads();
        sm[t] += u;
        __syncthreads();
    }
    g_bsum[t] = sm[t] - v;  // exclusive
}

__global__ void scan3_kernel() {      // block-local exclusive scan + offset
    __shared__ int sm[256];
    int t = threadIdx.x, b = blockIdx.x;
    int idx = b * 256 + t;
    int v = (idx < NN) ? g_deg[idx] : 0;
    sm[t] = v;
    __syncthreads();
    for (int off = 1; off < 256; off <<= 1) {
        int u = (t >= off) ? sm[t - off] : 0;
        __syncthreads();
        sm[t] += u;
        __syncthreads();
    }
    if (idx < NN) g_rowstart[idx] = g_bsum[b] + sm[t] - v;
    if (b == 0 && t == 0) g_rowstart[NN] = ET;
}

// ---------------- scatter: CSR src list grouped by dst ----------------
__global__ void scatter_kernel() {
    int e = blockIdx.x * blockDim.x + threadIdx.x;
    if (e >= ET) return;
    int d = g_dst[e];
    int pos = atomicAdd(&g_cursor[d], 1);
    g_csrsrc[g_rowstart[d] + pos] = g_src[e];
}

// ---------------- node LayerNorm ----------------
__global__ void ln_kernel(const float* __restrict__ X, const float* __restrict__ gamma,
                          const float* __restrict__ beta) {
    int n = blockIdx.x * (blockDim.x >> 5) + (threadIdx.x >> 5);
    if (n >= NN) return;
    int lane = threadIdx.x & 31;
    float4 v = ((const float4*)(X + (size_t)n * FIN))[lane];
    float s = v.x + v.y + v.z + v.w;
#pragma unroll
    for (int off = 16; off >= 1; off >>= 1) s += __shfl_xor_sync(0xffffffffu, s, off);
    float mu = s * (1.0f / FIN);
    float q = (v.x - mu) * (v.x - mu) + (v.y - mu) * (v.y - mu) +
              (v.z - mu) * (v.z - mu) + (v.w - mu) * (v.w - mu);
#pragma unroll
    for (int off = 16; off >= 1; off >>= 1) q += __shfl_xor_sync(0xffffffffu, q, off);
    float rstd = rsqrtf(q * (1.0f / FIN) + LN_EPS);
    float4 g = ((const float4*)gamma)[lane];
    float4 b = ((const float4*)beta)[lane];
    float4 o;
    o.x = (v.x - mu) * rstd * g.x + b.x;
    o.y = (v.y - mu) * rstd * g.y + b.y;
    o.z = (v.z - mu) * rstd * g.z + b.z;
    o.w = (v.w - mu) * rstd * g.w + b.w;
    ((float4*)(g_xn + (size_t)n * FIN))[lane] = o;
}

// ---------------- regime LN + rank-1 contribution ----------------
__global__ void prep_kernel(const float* __restrict__ reg, const float* __restrict__ rg,
                            const float* __restrict__ rb, const float* __restrict__ W1) {
    __shared__ float rn[RD];
    __shared__ float s_mu, s_rstd;
    int tid = threadIdx.x;
    if (tid == 0) {
        float s = 0.f;
        for (int k = 0; k < RD; k++) s += reg[k];
        float mu = s / RD;
        float q = 0.f;
        for (int k = 0; k < RD; k++) { float d = reg[k] - mu; q += d * d; }
        s_mu = mu; s_rstd = rsqrtf(q / RD + LN_EPS);
    }
    __syncthreads();
    if (tid < RD) rn[tid] = (reg[tid] - s_mu) * s_rstd * rg[tid] + rb[tid];
    __syncthreads();
    float acc = 0.f;
    for (int k = 0; k < RD; k++) acc += rn[k] * W1[(size_t)(FIN + k) * D1 + tid];
    g_rc[tid] = acc;
}

// ---------------- GEMM1: xw1 = g_xn @ W1[:128] + rc (fp32 + bf16 copy) ----------------
__global__ void gemm1_kernel(const float* __restrict__ W1) {
    __shared__ float As[64][68];
    __shared__ float Bs[64][64];
    int row0 = blockIdx.y * 64;
    int col0 = blockIdx.x * 64;
    int tid = threadIdx.x;
    int ty4 = (tid >> 4) * 4, tx4 = (tid & 15) * 4;
    float acc[4][4] = {};
    for (int kc = 0; kc < 2; kc++) {
#pragma unroll
        for (int it = 0; it < 4; it++) {
            int flat = it * 1024 + tid * 4;
            int r = flat >> 6, c = flat & 63;
            float4 v = make_float4(0.f, 0.f, 0.f, 0.f);
            if (row0 + r < NN)
                v = *(const float4*)(g_xn + (size_t)(row0 + r) * FIN + kc * 64 + c);
            *(float4*)&As[r][c] = v;
            *(float4*)&Bs[r][c] = *(const float4*)(W1 + (size_t)(kc * 64 + r) * D1 + col0 + c);
        }
        __syncthreads();
#pragma unroll 4
        for (int k = 0; k < 64; k++) {
            float a[4];
#pragma unroll
            for (int i = 0; i < 4; i++) a[i] = As[ty4 + i][k];
            float4 b = *(const float4*)&Bs[k][tx4];
#pragma unroll
            for (int i = 0; i < 4; i++) {
                acc[i][0] += a[i] * b.x; acc[i][1] += a[i] * b.y;
                acc[i][2] += a[i] * b.z; acc[i][3] += a[i] * b.w;
            }
        }
        __syncthreads();
    }
    float4 rc = *(const float4*)&g_rc[col0 + tx4];
#pragma unroll
    for (int i = 0; i < 4; i++) {
        int r = row0 + ty4 + i;
        if (r < NN) {
            float4 o = make_float4(acc[i][0] + rc.x, acc[i][1] + rc.y,
                                   acc[i][2] + rc.z, acc[i][3] + rc.w);
            *(float4*)&g_xw1[(size_t)r * D1 + col0 + tx4] = o;
            __nv_bfloat162 blo = __float22bfloat162_rn(make_float2(o.x, o.y));
            __nv_bfloat162 bhi = __float22bfloat162_rn(make_float2(o.z, o.w));
            uint2 pk = make_uint2(*(unsigned*)&blo, *(unsigned*)&bhi);
            *(uint2*)&g_xw1b[(size_t)r * D1 + col0 + tx4] = pk;
        }
    }
}

// ---------------- alpha1 ----------------
__global__ void alpha1_kernel(const float* __restrict__ a_src, const float* __restrict__ a_dst) {
    int n = blockIdx.x * (blockDim.x >> 5) + (threadIdx.x >> 5);
    if (n >= NN) return;
    int lane = threadIdx.x & 31;
    const float4* xr = (const float4*)&g_xw1[(size_t)n * D1];
    float4 x0 = xr[lane], x1 = xr[lane + 32];
    float4 s0 = ((const float4*)a_src)[lane], s1 = ((const float4*)a_src)[lane + 32];
    float4 d0 = ((const float4*)a_dst)[lane], d1 = ((const float4*)a_dst)[lane + 32];
    float ss0 = x0.x * s0.x + x0.y * s0.y + x0.z * s0.z + x0.w * s0.w;
    float ss1 = x1.x * s1.x + x1.y * s1.y + x1.z * s1.z + x1.w * s1.w;
    float dd0 = x0.x * d0.x + x0.y * d0.y + x0.z * d0.z + x0.w * d0.w;
    float dd1 = x1.x * d1.x + x1.y * d1.y + x1.z * d1.z + x1.w * d1.w;
#pragma unroll
    for (int off = 8; off >= 1; off >>= 1) {
        ss0 += __shfl_xor_sync(0xffffffffu, ss0, off);
        ss1 += __shfl_xor_sync(0xffffffffu, ss1, off);
        dd0 += __shfl_xor_sync(0xffffffffu, dd0, off);
        dd1 += __shfl_xor_sync(0xffffffffu, dd1, off);
    }
    if ((lane & 15) == 0) {
        int g = lane >> 4;
        g_as1[n * 4 + g] = ss0;     g_as1[n * 4 + 2 + g] = ss1;
        g_ad1[n * 4 + g] = dd0;     g_ad1[n * 4 + 2 + g] = dd1;
    }
}

// ---------------- fused layer-1 aggregation (bf16 gather) ----------------
__global__ void agg1_kernel(const float* __restrict__ b1) {
    __shared__ float4 s_ex[8][32];
    __shared__ int    s_src[8][32];
    int warp = threadIdx.x >> 5;
    int lane = threadIdx.x & 31;
    int n = blockIdx.x * 8 + warp;
    if (n >= NN) return;
    int beg = g_rowstart[n], end = g_rowstart[n + 1];
    float4 ad = *(const float4*)&g_ad1[n * 4];

    float4 mx = make_float4(NEGINF, NEGINF, NEGINF, NEGINF);
    for (int i = beg + lane; i < end; i += 32) {
        int s = g_csrsrc[i];
        float4 as = *(const float4*)&g_as1[s * 4];
        mx.x = fmaxf(mx.x, lrelu(as.x + ad.x));
        mx.y = fmaxf(mx.y, lrelu(as.y + ad.y));
        mx.z = fmaxf(mx.z, lrelu(as.z + ad.z));
        mx.w = fmaxf(mx.w, lrelu(as.w + ad.w));
    }
#pragma unroll
    for (int off = 16; off >= 1; off >>= 1) {
        mx.x = fmaxf(mx.x, __shfl_xor_sync(0xffffffffu, mx.x, off));
        mx.y = fmaxf(mx.y, __shfl_xor_sync(0xffffffffu, mx.y, off));
        mx.z = fmaxf(mx.z, __shfl_xor_sync(0xffffffffu, mx.z, off));
        mx.w = fmaxf(mx.w, __shfl_xor_sync(0xffffffffu, mx.w, off));
    }

    float4 den = make_float4(0.f, 0.f, 0.f, 0.f);
    float4 accLo = make_float4(0.f, 0.f, 0.f, 0.f);
    float4 accHi = make_float4(0.f, 0.f, 0.f, 0.f);
    for (int chunk = beg; chunk < end; chunk += 32) {
        int m = min(32, end - chunk);
        if (lane < m) {
            int s = g_csrsrc[chunk + lane];
            float4 as = *(const float4*)&g_as1[s * 4];
            float4 ex;
            ex.x = expf(lrelu(as.x + ad.x) - mx.x);
            ex.y = expf(lrelu(as.y + ad.y) - mx.y);
            ex.z = expf(lrelu(as.z + ad.z) - mx.z);
            ex.w = expf(lrelu(as.w + ad.w) - mx.w);
            den.x += ex.x; den.y += ex.y; den.z += ex.z; den.w += ex.w;
            s_ex[warp][lane] = ex;
            s_src[warp][lane] = s;
        }
        __syncwarp();
        for (int j = 0; j < m; j++) {
            int s = s_src[warp][j];
            float4 ex = s_ex[warp][j];
            float wlo = (lane < 16) ? ex.x : ex.y;
            float whi = (lane < 16) ? ex.z : ex.w;
            const uint2* xs = (const uint2*)&g_xw1b[(size_t)s * D1];
            uint2 p0 = xs[lane];
            uint2 p1 = xs[lane + 32];
            float2 a0 = __bfloat1622float2(*(__nv_bfloat162*)&p0.x);
            float2 a1 = __bfloat1622float2(*(__nv_bfloat162*)&p0.y);
            float2 a2 = __bfloat1622float2(*(__nv_bfloat162*)&p1.x);
            float2 a3 = __bfloat1622float2(*(__nv_bfloat162*)&p1.y);
            accLo.x += wlo * a0.x; accLo.y += wlo * a0.y;
            accLo.z += wlo * a1.x; accLo.w += wlo * a1.y;
            accHi.x += whi * a2.x; accHi.y += whi * a2.y;
            accHi.z += whi * a3.x; accHi.w += whi * a3.y;
        }
        __syncwarp();
    }
#pragma unroll
    for (int off = 16; off >= 1; off >>= 1) {
        den.x += __shfl_xor_sync(0xffffffffu, den.x, off);
        den.y += __shfl_xor_sync(0xffffffffu, den.y, off);
        den.z += __shfl_xor_sync(0xffffffffu, den.z, off);
        den.w += __shfl_xor_sync(0xffffffffu, den.w, off);
    }
    float rlo = 1.0f / ((lane < 16) ? den.x : den.y);
    float rhi = 1.0f / ((lane < 16) ? den.z : den.w);
    float4 blo = ((const float4*)b1)[lane];
    float4 bhi = ((const float4*)b1)[lane + 32];
    float4 o0, o1;
    o0.x = eluf(accLo.x * rlo + blo.x); o0.y = eluf(accLo.y * rlo + blo.y);
    o0.z = eluf(accLo.z * rlo + blo.z); o0.w = eluf(accLo.w * rlo + blo.w);
    o1.x = eluf(accHi.x * rhi + bhi.x); o1.y = eluf(accHi.y * rhi + bhi.y);
    o1.z = eluf(accHi.z * rhi + bhi.z); o1.w = eluf(accHi.w * rhi + bhi.w);
    float4* od = (float4*)&g_h1[(size_t)n * D1];
    od[lane] = o0;
    od[lane + 32] = o1;
}

// ---------------- GEMM2: xw2 = g_h1 @ W2 (fp32 + bf16 copy) ----------------
__global__ void gemm2_kernel(const float* __restrict__ W2) {
    __shared__ float As[64][68];
    __shared__ float Bs[64][64];
    int row0 = blockIdx.x * 64;
    int tid = threadIdx.x;
    int ty4 = (tid >> 4) * 4, tx4 = (tid & 15) * 4;
    float acc[4][4] = {};
    for (int kc = 0; kc < 4; kc++) {
#pragma unroll
        for (int it = 0; it < 4; it++) {
            int flat = it * 1024 + tid * 4;
            int r = flat >> 6, c = flat & 63;
            float4 v = make_float4(0.f, 0.f, 0.f, 0.f);
            if (row0 + r < NN)
                v = *(const float4*)&g_h1[(size_t)(row0 + r) * D1 + kc * 64 + c];
            *(float4*)&As[r][c] = v;
            *(float4*)&Bs[r][c] = *(const float4*)(W2 + (size_t)(kc * 64 + r) * D2 + c);
        }
        __syncthreads();
#pragma unroll 4
        for (int k = 0; k < 64; k++) {
            float a[4];
#pragma unroll
            for (int i = 0; i < 4; i++) a[i] = As[ty4 + i][k];
            float4 b = *(const float4*)&Bs[k][tx4];
#pragma unroll
            for (int i = 0; i < 4; i++) {
                acc[i][0] += a[i] * b.x; acc[i][1] += a[i] * b.y;
                acc[i][2] += a[i] * b.z; acc[i][3] += a[i] * b.w;
            }
        }
        __syncthreads();
    }
#pragma unroll
    for (int i = 0; i < 4; i++) {
        int r = row0 + ty4 + i;
        if (r < NN) {
            float4 o = make_float4(acc[i][0], acc[i][1], acc[i][2], acc[i][3]);
            *(float4*)&g_xw2[(size_t)r * D2 + tx4] = o;
            __nv_bfloat162 blo = __float22bfloat162_rn(make_float2(o.x, o.y));
            __nv_bfloat162 bhi = __float22bfloat162_rn(make_float2(o.z, o.w));
            uint2 pk = make_uint2(*(unsigned*)&blo, *(unsigned*)&bhi);
            *(uint2*)&g_xw2b[(size_t)r * D2 + tx4] = pk;
        }
    }
}

// ---------------- alpha2 ----------------
__global__ void alpha2_kernel(const float* __restrict__ a_src, const float* __restrict__ a_dst) {
    int n = blockIdx.x * (blockDim.x >> 5) + (threadIdx.x >> 5);
    if (n >= NN) return;
    int lane = threadIdx.x & 31;
    float2 x = ((const float2*)&g_xw2[(size_t)n * D2])[lane];
    float2 s = ((const float2*)a_src)[lane];
    float2 d = ((const float2*)a_dst)[lane];
    float ss = x.x * s.x + x.y * s.y;
    float dd = x.x * d.x + x.y * d.y;
#pragma unroll
    for (int off = 16; off >= 1; off >>= 1) {
        ss += __shfl_xor_sync(0xffffffffu, ss, off);
        dd += __shfl_xor_sync(0xffffffffu, dd, off);
    }
    if (lane == 0) { g_as2[n] = ss; g_ad2[n] = dd; }
}

// ---------------- fused layer-2 aggregation + logits (bf16 gather) ----------------
__global__ void agg2_kernel(const float* __restrict__ b2, const float* __restrict__ Wout,
                            const float* __restrict__ bout, float* __restrict__ out) {
    __shared__ float s_ex[8][32];
    __shared__ int   s_src[8][32];
    int warp = threadIdx.x >> 5;
    int lane = threadIdx.x & 31;
    int n = blockIdx.x * 8 + warp;
    if (n >= NN) return;
    int beg = g_rowstart[n], end = g_rowstart[n + 1];
    float ad = g_ad2[n];

    float mx = NEGINF;
    for (int i = beg + lane; i < end; i += 32) {
        int s = g_csrsrc[i];
        mx = fmaxf(mx, lrelu(g_as2[s] + ad));
    }
#pragma unroll
    for (int off = 16; off >= 1; off >>= 1)
        mx = fmaxf(mx, __shfl_xor_sync(0xffffffffu, mx, off));

    float den = 0.f;
    float2 acc = make_float2(0.f, 0.f);
    for (int chunk = beg; chunk < end; chunk += 32) {
        int m = min(32, end - chunk);
        if (lane < m) {
            int s = g_csrsrc[chunk + lane];
            float ex = expf(lrelu(g_as2[s] + ad) - mx);
            den += ex;
            s_ex[warp][lane] = ex;
            s_src[warp][lane] = s;
        }
        __syncwarp();
        for (int j = 0; j < m; j++) {
            int s = s_src[warp][j];
            float w = s_ex[warp][j];
            unsigned pk = ((const unsigned*)&g_xw2b[(size_t)s * D2])[lane];
            float2 v = __bfloat1622float2(*(__nv_bfloat162*)&pk);
            acc.x += w * v.x;
            acc.y += w * v.y;
        }
        __syncwarp();
    }
#pragma unroll
    for (int off = 16; off >= 1; off >>= 1)
        den += __shfl_xor_sync(0xffffffffu, den, off);
    float r = 1.0f / den;
    float2 bb = ((const float2*)b2)[lane];
    float2 w = ((const float2*)Wout)[lane];
    float p = eluf(acc.x * r + bb.x) * w.x + eluf(acc.y * r + bb.y) * w.y;
#pragma unroll
    for (int off = 16; off >= 1; off >>= 1)
        p += __shfl_xor_sync(0xffffffffu, p, off);
    if (lane == 0) {
        float logit = p + bout[0];
        out[NN + n] = logit;
        atomicMax(&g_smax, encf(logit));
    }
}

// ---------------- global softmax epilogue ----------------
__global__ void expw_kernel(const float* __restrict__ out) {
    int n = blockIdx.x * blockDim.x + threadIdx.x;
    if (n >= NN) return;
    float mx = decf(g_smax);
    float ex = expf(out[NN + n] - mx);
    g_expw[n] = ex;
    atomicAdd(&g_ssum, ex);
}

__global__ void weights_kernel(float* __restrict__ out) {
    int n = blockIdx.x * blockDim.x + threadIdx.x;
    if (n >= NN) return;
    out[n] = g_expw[n] / g_ssum;
}

// ---------------- launch ----------------
extern "C" void kernel_launch(void* const* d_in, const int* in_sizes, int n_in,
                              void* d_out, int out_size) {
    const float* x      = (const float*)d_in[0];
    const void*  ei     = (const void*)d_in[1];
    const float* reg    = (const float*)d_in[2];
    const float* ngamma = (const float*)d_in[3];
    const float* nbeta  = (const float*)d_in[4];
    const float* rgamma = (const float*)d_in[5];
    const float* rbeta  = (const float*)d_in[6];
    const float* W1     = (const float*)d_in[7];
    const float* a_s1   = (const float*)d_in[8];
    const float* a_d1   = (const float*)d_in[9];
    const float* b1     = (const float*)d_in[10];
    const float* W2     = (const float*)d_in[11];
    const float* a_s2   = (const float*)d_in[12];
    const float* a_d2   = (const float*)d_in[13];
    const float* b2     = (const float*)d_in[14];
    const float* Wout   = (const float*)d_in[15];
    const float* bout   = (const float*)d_in[16];
    float* out = (float*)d_out;

    detect_kernel<<<1, 32>>>(ei);
    init_kernel<<<256, 256>>>();
    convert_kernel<<<(ET + 255) / 256, 256>>>(ei);
    scan1_kernel<<<NBLK, 256>>>();
    scan2_kernel<<<1, 256>>>();
    scan3_kernel<<<NBLK, 256>>>();
    scatter_kernel<<<(ET + 255) / 256, 256>>>();

    ln_kernel<<<(NN + 7) / 8, 256>>>(x, ngamma, nbeta);
    prep_kernel<<<1, 256>>>(reg, rgamma, rbeta, W1);

    dim3 g1(4, (NN + 63) / 64);
    gemm1_kernel<<<g1, 256>>>(W1);
    alpha1_kernel<<<(NN + 7) / 8, 256>>>(a_s1, a_d1);

    agg1_kernel<<<(NN + 7) / 8, 256>>>(b1);

    gemm2_kernel<<<(NN + 63) / 64, 256>>>(W2);
    alpha2_kernel<<<(NN + 7) / 8, 256>>>(a_s2, a_d2);

    agg2_kernel<<<(NN + 7) / 8, 256>>>(b2, Wout, bout, out);

    expw_kernel<<<(NN + 255) / 256, 256>>>(out);
    weights_kernel<<<(NN + 255) / 256, 256>>>(out);
}

// round 6
// speedup vs baseline: 1.9498x; 1.0087x over previous
#include <cuda_runtime.h>
#include <math.h>

#define NN 50000
#define EE 1600000
#define ET (EE + NN)
#define FIN 128
#define RD 16
#define HID 64
#define HEADS 4
#define D1 256
#define D2 64
#define NEG 0.2f
#define LN_EPS 1e-5f
#define IMIN (-2147483647 - 1)
#define NEGINF (-3.402823466e38f)
#define NBLK 196   // ceil(NN/256)
#define BM 128
#define BN 64
#define BK 32

// ---------------- scratch ----------------
__device__ float g_xn[(size_t)NN * FIN];
__device__ float g_xw1[(size_t)NN * D1];
__device__ float g_h1[(size_t)NN * D1];
__device__ float g_as1[NN * HEADS];
__device__ float g_ad1[NN * HEADS];
__device__ float g_xw2[(size_t)NN * D2];
__device__ float g_as2[NN];
__device__ float g_ad2[NN];
__device__ float g_rc[D1];
__device__ int   g_smax;
__device__ float g_ssum;
__device__ float g_expw[NN];
__device__ int   g_src[ET];
__device__ int   g_dst[ET];
__device__ int   g_deg[NN];
__device__ int   g_rowstart[NN + 1];
__device__ int   g_cursor[NN];
__device__ int   g_csrsrc[ET];
__device__ int   g_bsum[256];
__device__ int   g_is64;

// ---------------- helpers ----------------
__device__ __forceinline__ int encf(float f) {
    int i = __float_as_int(f);
    return (i >= 0) ? i : (i ^ 0x7fffffff);
}
__device__ __forceinline__ float decf(int i) {
    return __int_as_float((i >= 0) ? i : (i ^ 0x7fffffff));
}
__device__ __forceinline__ float lrelu(float x) { return x > 0.f ? x : NEG * x; }
__device__ __forceinline__ float eluf(float x)  { return x > 0.f ? x : expm1f(x); }

// ---------------- node LayerNorm ----------------
__global__ void ln_kernel(const float* __restrict__ X, const float* __restrict__ gamma,
                          const float* __restrict__ beta) {
    int n = blockIdx.x * (blockDim.x >> 5) + (threadIdx.x >> 5);
    if (n >= NN) return;
    int lane = threadIdx.x & 31;
    float4 v = ((const float4*)(X + (size_t)n * FIN))[lane];
    float s = v.x + v.y + v.z + v.w;
#pragma unroll
    for (int off = 16; off >= 1; off >>= 1) s += __shfl_xor_sync(0xffffffffu, s, off);
    float mu = s * (1.0f / FIN);
    float q = (v.x - mu) * (v.x - mu) + (v.y - mu) * (v.y - mu) +
              (v.z - mu) * (v.z - mu) + (v.w - mu) * (v.w - mu);
#pragma unroll
    for (int off = 16; off >= 1; off >>= 1) q += __shfl_xor_sync(0xffffffffu, q, off);
    float rstd = rsqrtf(q * (1.0f / FIN) + LN_EPS);
    float4 g = ((const float4*)gamma)[lane];
    float4 b = ((const float4*)beta)[lane];
    float4 o;
    o.x = (v.x - mu) * rstd * g.x + b.x;
    o.y = (v.y - mu) * rstd * g.y + b.y;
    o.z = (v.z - mu) * rstd * g.z + b.z;
    o.w = (v.w - mu) * rstd * g.w + b.w;
    ((float4*)(g_xn + (size_t)n * FIN))[lane] = o;
}

// ---------------- regime LN + rank-1 contribution ----------------
__global__ void prep_kernel(const float* __restrict__ reg, const float* __restrict__ rg,
                            const float* __restrict__ rb, const float* __restrict__ W1) {
    __shared__ float rn[RD];
    __shared__ float s_mu, s_rstd;
    int tid = threadIdx.x;
    if (tid == 0) {
        float s = 0.f;
        for (int k = 0; k < RD; k++) s += reg[k];
        float mu = s / RD;
        float q = 0.f;
        for (int k = 0; k < RD; k++) { float d = reg[k] - mu; q += d * d; }
        s_mu = mu; s_rstd = rsqrtf(q / RD + LN_EPS);
    }
    __syncthreads();
    if (tid < RD) rn[tid] = (reg[tid] - s_mu) * s_rstd * rg[tid] + rb[tid];
    __syncthreads();
    float acc = 0.f;
    for (int k = 0; k < RD; k++) acc += rn[k] * W1[(size_t)(FIN + k) * D1 + tid];
    g_rc[tid] = acc;
}

// ---------------- edge dtype detect ----------------
__global__ void detect_kernel(const void* ei) {
    if (threadIdx.x == 0 && blockIdx.x == 0) {
        const long long* p = (const long long*)ei;
        int is64 = 1;
        for (int i = 0; i < 64; i++) {
            long long v = p[i];
            if (v < 0 || v >= 2147483648LL) { is64 = 0; break; }
        }
        g_is64 = is64;
    }
}

// ---------------- GEMM1: xw1 = g_xn @ W1[:128] + rc ----------------
// BM=128, BN=64, BK=32, 256 threads, 8x4 microtile
__global__ void gemm1_kernel(const float* __restrict__ W1) {
    __shared__ float As[BK][BM + 4];
    __shared__ float Bs[BK][BN];
    int row0 = blockIdx.y * BM;
    int col0 = blockIdx.x * BN;
    int tid = threadIdx.x;
    int tx = tid & 15, ty = tid >> 4;
    float acc[8][4] = {};
    for (int kc = 0; kc < FIN; kc += BK) {
#pragma unroll
        for (int it = 0; it < 4; it++) {
            int flat = it * 1024 + tid * 4;
            int r = flat >> 5, k = flat & 31;
            float4 v = make_float4(0.f, 0.f, 0.f, 0.f);
            if (row0 + r < NN)
                v = *(const float4*)(g_xn + (size_t)(row0 + r) * FIN + kc + k);
            As[k + 0][r] = v.x; As[k + 1][r] = v.y;
            As[k + 2][r] = v.z; As[k + 3][r] = v.w;
        }
#pragma unroll
        for (int it = 0; it < 2; it++) {
            int flat = it * 1024 + tid * 4;
            int k = flat >> 6, c = flat & 63;
            *(float4*)&Bs[k][c] = *(const float4*)(W1 + (size_t)(kc + k) * D1 + col0 + c);
        }
        __syncthreads();
#pragma unroll
        for (int k = 0; k < BK; k++) {
            float4 a0 = *(float4*)&As[k][ty * 8];
            float4 a1 = *(float4*)&As[k][ty * 8 + 4];
            float4 b  = *(float4*)&Bs[k][tx * 4];
            float av[8] = {a0.x, a0.y, a0.z, a0.w, a1.x, a1.y, a1.z, a1.w};
#pragma unroll
            for (int i = 0; i < 8; i++) {
                acc[i][0] += av[i] * b.x; acc[i][1] += av[i] * b.y;
                acc[i][2] += av[i] * b.z; acc[i][3] += av[i] * b.w;
            }
        }
        __syncthreads();
    }
    float4 rc = *(const float4*)&g_rc[col0 + tx * 4];
#pragma unroll
    for (int i = 0; i < 8; i++) {
        int r = row0 + ty * 8 + i;
        if (r < NN) {
            float4 o = make_float4(acc[i][0] + rc.x, acc[i][1] + rc.y,
                                   acc[i][2] + rc.z, acc[i][3] + rc.w);
            *(float4*)&g_xw1[(size_t)r * D1 + col0 + tx * 4] = o;
        }
    }
}

// ---------------- init ----------------
__global__ void init_kernel() {
    int i = blockIdx.x * blockDim.x + threadIdx.x;
    int stride = gridDim.x * blockDim.x;
    for (int t = i; t < NN; t += stride) { g_deg[t] = 0; g_cursor[t] = 0; }
    if (i == 0) { g_smax = IMIN; g_ssum = 0.f; }
}

// ---------------- convert edges + degree histogram ----------------
__global__ void convert_kernel(const void* ei) {
    int e = blockIdx.x * blockDim.x + threadIdx.x;
    if (e >= ET) return;
    int s, d;
    if (e < EE) {
        if (g_is64) {
            const long long* p = (const long long*)ei;
            s = (int)p[e];
            d = (int)p[(size_t)EE + e];
        } else {
            const int* p = (const int*)ei;
            s = p[e];
            d = p[EE + e];
        }
    } else {
        s = d = e - EE;
    }
    g_src[e] = s;
    g_dst[e] = d;
    atomicAdd(&g_deg[d], 1);
}

// ---------------- 3-phase coalesced exclusive scan ----------------
__global__ void scan1_kernel() {
    __shared__ int sm[256];
    int t = threadIdx.x, b = blockIdx.x;
    int idx = b * 256 + t;
    int v = (idx < NN) ? g_deg[idx] : 0;
    sm[t] = v;
    __syncthreads();
    for (int off = 128; off >= 1; off >>= 1) {
        if (t < off) sm[t] += sm[t + off];
        __syncthreads();
    }
    if (t == 0) g_bsum[b] = sm[0];
}

__global__ void scan2_kernel() {
    __shared__ int sm[256];
    int t = threadIdx.x;
    int v = (t < NBLK) ? g_bsum[t] : 0;
    sm[t] = v;
    __syncthreads();
    for (int off = 1; off < 256; off <<= 1) {
        int u = (t >= off) ? sm[t - off] : 0;
        __syncthreads();
        sm[t] += u;
        __syncthreads();
    }
    g_bsum[t] = sm[t] - v;
}

__global__ void scan3_kernel() {
    __shared__ int sm[256];
    int t = threadIdx.x, b = blockIdx.x;
    int idx = b * 256 + t;
    int v = (idx < NN) ? g_deg[idx] : 0;
    sm[t] = v;
    __syncthreads();
    for (int off = 1; off < 256; off <<= 1) {
        int u = (t >= off) ? sm[t - off] : 0;
        __syncthreads();
        sm[t] += u;
        __syncthreads();
    }
    if (idx < NN) g_rowstart[idx] = g_bsum[b] + sm[t] - v;
    if (b == 0 && t == 0) g_rowstart[NN] = ET;
}

// ---------------- scatter ----------------
__global__ void scatter_kernel() {
    int e = blockIdx.x * blockDim.x + threadIdx.x;
    if (e >= ET) return;
    int d = g_dst[e];
    int pos = atomicAdd(&g_cursor[d], 1);
    g_csrsrc[g_rowstart[d] + pos] = g_src[e];
}

// ---------------- alpha1 ----------------
__global__ void alpha1_kernel(const float* __restrict__ a_src, const float* __restrict__ a_dst) {
    int n = blockIdx.x * (blockDim.x >> 5) + (threadIdx.x >> 5);
    if (n >= NN) return;
    int lane = threadIdx.x & 31;
    const float4* xr = (const float4*)&g_xw1[(size_t)n * D1];
    float4 x0 = xr[lane], x1 = xr[lane + 32];
    float4 s0 = ((const float4*)a_src)[lane], s1 = ((const float4*)a_src)[lane + 32];
    float4 d0 = ((const float4*)a_dst)[lane], d1 = ((const float4*)a_dst)[lane + 32];
    float ss0 = x0.x * s0.x + x0.y * s0.y + x0.z * s0.z + x0.w * s0.w;
    float ss1 = x1.x * s1.x + x1.y * s1.y + x1.z * s1.z + x1.w * s1.w;
    float dd0 = x0.x * d0.x + x0.y * d0.y + x0.z * d0.z + x0.w * d0.w;
    float dd1 = x1.x * d1.x + x1.y * d1.y + x1.z * d1.z + x1.w * d1.w;
#pragma unroll
    for (int off = 8; off >= 1; off >>= 1) {
        ss0 += __shfl_xor_sync(0xffffffffu, ss0, off);
        ss1 += __shfl_xor_sync(0xffffffffu, ss1, off);
        dd0 += __shfl_xor_sync(0xffffffffu, dd0, off);
        dd1 += __shfl_xor_sync(0xffffffffu, dd1, off);
    }
    if ((lane & 15) == 0) {
        int g = lane >> 4;
        g_as1[n * 4 + g] = ss0;     g_as1[n * 4 + 2 + g] = ss1;
        g_ad1[n * 4 + g] = dd0;     g_ad1[n * 4 + 2 + g] = dd1;
    }
}

// ---------------- fused layer-1 aggregation (fp32 gather, unrolled) ----------------
__global__ void agg1_kernel(const float* __restrict__ b1) {
    __shared__ float4 s_ex[8][32];
    __shared__ int    s_src[8][32];
    int warp = threadIdx.x >> 5;
    int lane = threadIdx.x & 31;
    int n = blockIdx.x * 8 + warp;
    if (n >= NN) return;
    int beg = g_rowstart[n], end = g_rowstart[n + 1];
    float4 ad = *(const float4*)&g_ad1[n * 4];

    float4 mx = make_float4(NEGINF, NEGINF, NEGINF, NEGINF);
    for (int i = beg + lane; i < end; i += 32) {
        int s = g_csrsrc[i];
        float4 as = *(const float4*)&g_as1[s * 4];
        mx.x = fmaxf(mx.x, lrelu(as.x + ad.x));
        mx.y = fmaxf(mx.y, lrelu(as.y + ad.y));
        mx.z = fmaxf(mx.z, lrelu(as.z + ad.z));
        mx.w = fmaxf(mx.w, lrelu(as.w + ad.w));
    }
#pragma unroll
    for (int off = 16; off >= 1; off >>= 1) {
        mx.x = fmaxf(mx.x, __shfl_xor_sync(0xffffffffu, mx.x, off));
        mx.y = fmaxf(mx.y, __shfl_xor_sync(0xffffffffu, mx.y, off));
        mx.z = fmaxf(mx.z, __shfl_xor_sync(0xffffffffu, mx.z, off));
        mx.w = fmaxf(mx.w, __shfl_xor_sync(0xffffffffu, mx.w, off));
    }

    float4 den = make_float4(0.f, 0.f, 0.f, 0.f);
    float4 accLo = make_float4(0.f, 0.f, 0.f, 0.f);
    float4 accHi = make_float4(0.f, 0.f, 0.f, 0.f);
    for (int chunk = beg; chunk < end; chunk += 32) {
        int m = min(32, end - chunk);
        if (lane < m) {
            int s = g_csrsrc[chunk + lane];
            float4 as = *(const float4*)&g_as1[s * 4];
            float4 ex;
            ex.x = expf(lrelu(as.x + ad.x) - mx.x);
            ex.y = expf(lrelu(as.y + ad.y) - mx.y);
            ex.z = expf(lrelu(as.z + ad.z) - mx.z);
            ex.w = expf(lrelu(as.w + ad.w) - mx.w);
            den.x += ex.x; den.y += ex.y; den.z += ex.z; den.w += ex.w;
            s_ex[warp][lane] = ex;
            s_src[warp][lane] = s;
        }
        __syncwarp();
        int j = 0;
        for (; j + 2 <= m; j += 2) {
            int s0 = s_src[warp][j],     s1 = s_src[warp][j + 1];
            float4 e0 = s_ex[warp][j],   e1 = s_ex[warp][j + 1];
            float w0lo = (lane < 16) ? e0.x : e0.y;
            float w0hi = (lane < 16) ? e0.z : e0.w;
            float w1lo = (lane < 16) ? e1.x : e1.y;
            float w1hi = (lane < 16) ? e1.z : e1.w;
            const float4* x0 = (const float4*)&g_xw1[(size_t)s0 * D1];
            const float4* x1 = (const float4*)&g_xw1[(size_t)s1 * D1];
            float4 v0a = x0[lane], v0b = x0[lane + 32];
            float4 v1a = x1[lane], v1b = x1[lane + 32];
            accLo.x += w0lo * v0a.x + w1lo * v1a.x;
            accLo.y += w0lo * v0a.y + w1lo * v1a.y;
            accLo.z += w0lo * v0a.z + w1lo * v1a.z;
            accLo.w += w0lo * v0a.w + w1lo * v1a.w;
            accHi.x += w0hi * v0b.x + w1hi * v1b.x;
            accHi.y += w0hi * v0b.y + w1hi * v1b.y;
            accHi.z += w0hi * v0b.z + w1hi * v1b.z;
            accHi.w += w0hi * v0b.w + w1hi * v1b.w;
        }
        if (j < m) {
            int s0 = s_src[warp][j];
            float4 e0 = s_ex[warp][j];
            float wlo = (lane < 16) ? e0.x : e0.y;
            float whi = (lane < 16) ? e0.z : e0.w;
            const float4* x0 = (const float4*)&g_xw1[(size_t)s0 * D1];
            float4 v0 = x0[lane], v1 = x0[lane + 32];
            accLo.x += wlo * v0.x; accLo.y += wlo * v0.y;
            accLo.z += wlo * v0.z; accLo.w += wlo * v0.w;
            accHi.x += whi * v1.x; accHi.y += whi * v1.y;
            accHi.z += whi * v1.z; accHi.w += whi * v1.w;
        }
        __syncwarp();
    }
#pragma unroll
    for (int off = 16; off >= 1; off >>= 1) {
        den.x += __shfl_xor_sync(0xffffffffu, den.x, off);
        den.y += __shfl_xor_sync(0xffffffffu, den.y, off);
        den.z += __shfl_xor_sync(0xffffffffu, den.z, off);
        den.w += __shfl_xor_sync(0xffffffffu, den.w, off);
    }
    float rlo = 1.0f / ((lane < 16) ? den.x : den.y);
    float rhi = 1.0f / ((lane < 16) ? den.z : den.w);
    float4 blo = ((const float4*)b1)[lane];
    float4 bhi = ((const float4*)b1)[lane + 32];
    float4 o0, o1;
    o0.x = eluf(accLo.x * rlo + blo.x); o0.y = eluf(accLo.y * rlo + blo.y);
    o0.z = eluf(accLo.z * rlo + blo.z); o0.w = eluf(accLo.w * rlo + blo.w);
    o1.x = eluf(accHi.x * rhi + bhi.x); o1.y = eluf(accHi.y * rhi + bhi.y);
    o1.z = eluf(accHi.z * rhi + bhi.z); o1.w = eluf(accHi.w * rhi + bhi.w);
    float4* od = (float4*)&g_h1[(size_t)n * D1];
    od[lane] = o0;
    od[lane + 32] = o1;
}

// ---------------- GEMM2: xw2 = g_h1 @ W2 ----------------
// BM=128, BN=64=D2, K=256, 256 threads, 8x4 microtile
__global__ void gemm2_kernel(const float* __restrict__ W2) {
    __shared__ float As[BK][BM + 4];
    __shared__ float Bs[BK][BN];
    int row0 = blockIdx.x * BM;
    int tid = threadIdx.x;
    int tx = tid & 15, ty = tid >> 4;
    float acc[8][4] = {};
    for (int kc = 0; kc < D1; kc += BK) {
#pragma unroll
        for (int it = 0; it < 4; it++) {
            int flat = it * 1024 + tid * 4;
            int r = flat >> 5, k = flat & 31;
            float4 v = make_float4(0.f, 0.f, 0.f, 0.f);
            if (row0 + r < NN)
                v = *(const float4*)(g_h1 + (size_t)(row0 + r) * D1 + kc + k);
            As[k + 0][r] = v.x; As[k + 1][r] = v.y;
            As[k + 2][r] = v.z; As[k + 3][r] = v.w;
        }
#pragma unroll
        for (int it = 0; it < 2; it++) {
            int flat = it * 1024 + tid * 4;
            int k = flat >> 6, c = flat & 63;
            *(float4*)&Bs[k][c] = *(const float4*)(W2 + (size_t)(kc + k) * D2 + c);
        }
        __syncthreads();
#pragma unroll
        for (int k = 0; k < BK; k++) {
            float4 a0 = *(float4*)&As[k][ty * 8];
            float4 a1 = *(float4*)&As[k][ty * 8 + 4];
            float4 b  = *(float4*)&Bs[k][tx * 4];
            float av[8] = {a0.x, a0.y, a0.z, a0.w, a1.x, a1.y, a1.z, a1.w};
#pragma unroll
            for (int i = 0; i < 8; i++) {
                acc[i][0] += av[i] * b.x; acc[i][1] += av[i] * b.y;
                acc[i][2] += av[i] * b.z; acc[i][3] += av[i] * b.w;
            }
        }
        __syncthreads();
    }
#pragma unroll
    for (int i = 0; i < 8; i++) {
        int r = row0 + ty * 8 + i;
        if (r < NN) {
            float4 o = make_float4(acc[i][0], acc[i][1], acc[i][2], acc[i][3]);
            *(float4*)&g_xw2[(size_t)r * D2 + tx * 4] = o;
        }
    }
}

// ---------------- alpha2 ----------------
__global__ void alpha2_kernel(const float* __restrict__ a_src, const float* __restrict__ a_dst) {
    int n = blockIdx.x * (blockDim.x >> 5) + (threadIdx.x >> 5);
    if (n >= NN) return;
    int lane = threadIdx.x & 31;
    float2 x = ((const float2*)&g_xw2[(size_t)n * D2])[lane];
    float2 s = ((const float2*)a_src)[lane];
    float2 d = ((const float2*)a_dst)[lane];
    float ss = x.x * s.x + x.y * s.y;
    float dd = x.x * d.x + x.y * d.y;
#pragma unroll
    for (int off = 16; off >= 1; off >>= 1) {
        ss += __shfl_xor_sync(0xffffffffu, ss, off);
        dd += __shfl_xor_sync(0xffffffffu, dd, off);
    }
    if (lane == 0) { g_as2[n] = ss; g_ad2[n] = dd; }
}

// ---------------- fused layer-2 aggregation + logits (fp32 gather) ----------------
__global__ void agg2_kernel(const float* __restrict__ b2, const float* __restrict__ Wout,
                            const float* __restrict__ bout, float* __restrict__ out) {
    __shared__ float s_ex[8][32];
    __shared__ int   s_src[8][32];
    int warp = threadIdx.x >> 5;
    int lane = threadIdx.x & 31;
    int n = blockIdx.x * 8 + warp;
    if (n >= NN) return;
    int beg = g_rowstart[n], end = g_rowstart[n + 1];
    float ad = g_ad2[n];

    float mx = NEGINF;
    for (int i = beg + lane; i < end; i += 32) {
        int s = g_csrsrc[i];
        mx = fmaxf(mx, lrelu(g_as2[s] + ad));
    }
#pragma unroll
    for (int off = 16; off >= 1; off >>= 1)
        mx = fmaxf(mx, __shfl_xor_sync(0xffffffffu, mx, off));

    float den = 0.f;
    float2 acc = make_float2(0.f, 0.f);
    for (int chunk = beg; chunk < end; chunk += 32) {
        int m = min(32, end - chunk);
        if (lane < m) {
            int s = g_csrsrc[chunk + lane];
            float ex = expf(lrelu(g_as2[s] + ad) - mx);
            den += ex;
            s_ex[warp][lane] = ex;
            s_src[warp][lane] = s;
        }
        __syncwarp();
        int j = 0;
        for (; j + 2 <= m; j += 2) {
            int s0 = s_src[warp][j], s1 = s_src[warp][j + 1];
            float w0 = s_ex[warp][j], w1 = s_ex[warp][j + 1];
            float2 v0 = ((const float2*)&g_xw2[(size_t)s0 * D2])[lane];
            float2 v1 = ((const float2*)&g_xw2[(size_t)s1 * D2])[lane];
            acc.x += w0 * v0.x + w1 * v1.x;
            acc.y += w0 * v0.y + w1 * v1.y;
        }
        if (j < m) {
            int s0 = s_src[warp][j];
            float w0 = s_ex[warp][j];
            float2 v0 = ((const float2*)&g_xw2[(size_t)s0 * D2])[lane];
            acc.x += w0 * v0.x;
            acc.y += w0 * v0.y;
        }
        __syncwarp();
    }
#pragma unroll
    for (int off = 16; off >= 1; off >>= 1)
        den += __shfl_xor_sync(0xffffffffu, den, off);
    float r = 1.0f / den;
    float2 bb = ((const float2*)b2)[lane];
    float2 w = ((const float2*)Wout)[lane];
    float p = eluf(acc.x * r + bb.x) * w.x + eluf(acc.y * r + bb.y) * w.y;
#pragma unroll
    for (int off = 16; off >= 1; off >>= 1)
        p += __shfl_xor_sync(0xffffffffu, p, off);
    if (lane == 0) {
        float logit = p + bout[0];
        out[NN + n] = logit;
        atomicMax(&g_smax, encf(logit));
    }
}

// ---------------- global softmax epilogue ----------------
__global__ void expw_kernel(const float* __restrict__ out) {
    int n = blockIdx.x * blockDim.x + threadIdx.x;
    if (n >= NN) return;
    float mx = decf(g_smax);
    float ex = expf(out[NN + n] - mx);
    g_expw[n] = ex;
    atomicAdd(&g_ssum, ex);
}

__global__ void weights_kernel(float* __restrict__ out) {
    int n = blockIdx.x * blockDim.x + threadIdx.x;
    if (n >= NN) return;
    out[n] = g_expw[n] / g_ssum;
}

// ---------------- launch ----------------
extern "C" void kernel_launch(void* const* d_in, const int* in_sizes, int n_in,
                              void* d_out, int out_size) {
    const float* x      = (const float*)d_in[0];
    const void*  ei     = (const void*)d_in[1];
    const float* reg    = (const float*)d_in[2];
    const float* ngamma = (const float*)d_in[3];
    const float* nbeta  = (const float*)d_in[4];
    const float* rgamma = (const float*)d_in[5];
    const float* rbeta  = (const float*)d_in[6];
    const float* W1     = (const float*)d_in[7];
    const float* a_s1   = (const float*)d_in[8];
    const float* a_d1   = (const float*)d_in[9];
    const float* b1     = (const float*)d_in[10];
    const float* W2     = (const float*)d_in[11];
    const float* a_s2   = (const float*)d_in[12];
    const float* a_d2   = (const float*)d_in[13];
    const float* b2     = (const float*)d_in[14];
    const float* Wout   = (const float*)d_in[15];
    const float* bout   = (const float*)d_in[16];
    float* out = (float*)d_out;

    // order chosen so launch index 3 (captured by ncu) is gemm1_kernel
    ln_kernel<<<(NN + 7) / 8, 256>>>(x, ngamma, nbeta);          // 0
    prep_kernel<<<1, 256>>>(reg, rgamma, rbeta, W1);             // 1
    detect_kernel<<<1, 32>>>(ei);                                // 2
    dim3 g1(D1 / BN, (NN + BM - 1) / BM);
    gemm1_kernel<<<g1, 256>>>(W1);                               // 3  <-- profiled
    init_kernel<<<256, 256>>>();                                 // 4
    convert_kernel<<<(ET + 255) / 256, 256>>>(ei);               // 5
    scan1_kernel<<<NBLK, 256>>>();                               // 6
    scan2_kernel<<<1, 256>>>();                                  // 7
    scan3_kernel<<<NBLK, 256>>>();                               // 8
    scatter_kernel<<<(ET + 255) / 256, 256>>>();                 // 9
    alpha1_kernel<<<(NN + 7) / 8, 256>>>(a_s1, a_d1);            // 10
    agg1_kernel<<<(NN + 7) / 8, 256>>>(b1);                      // 11
    gemm2_kernel<<<(NN + BM - 1) / BM, 256>>>(W2);               // 12
    alpha2_kernel<<<(NN + 7) / 8, 256>>>(a_s2, a_d2);            // 13
    agg2_kernel<<<(NN + 7) / 8, 256>>>(b2, Wout, bout, out);     // 14
    expw_kernel<<<(NN + 255) / 256, 256>>>(out);                 // 15
    weights_kernel<<<(NN + 255) / 256, 256>>>(out);              // 16
}